// round 11
// baseline (speedup 1.0000x reference)
#include <cuda_runtime.h>
#include <cstdint>

#define Bsz 512
#define Nn  8192
#define CH  16
#define NC  (Nn / CH)

// Scratch (static __device__ per harness rules)
__device__ float2 g_lplq[(size_t)Bsz * Nn];   // (lp_i, lq_i) transposed [i][b]
__device__ float  g_r   [(size_t)Bsz * Nn];   // r_i = x1_i - A1_i, layout [b][i]

__device__ __forceinline__ float neg_inf_f() { return __int_as_float(0xff800000); }

// log1mexp(x) = log(1 - e^x), x <= 0, matching the reference's branch structure
__device__ __forceinline__ float log1mexp_f(float x) {
    return (x > -0.69314718f) ? logf(-expm1f(x)) : log1pf(-expf(x));
}

// ---------------------------------------------------------------------------
// Custom branch-free softplus(-|dd|) = log1p(exp(-|dd|)), FMA-only Estrin.
// Dependent-chain ~70cy vs ~110cy for libdevice log1pf(expf(.)).
// |err| <= ~3e-7 absolute per step -- same scale as the R8 MUFU drift that
// produced ZERO selection flips (rel_err 0.0). dd/x2/A0/m keep the exact
// reference rounding; only the softplus tail is approximated.
// Handles dd = +inf (step 1): a clamps to -126 -> e ~ 2^-126 -> t ~ 0. No NaN.
// ---------------------------------------------------------------------------
__device__ __forceinline__ float softplus_tail(float dd) {
    // ---- e = exp(-|dd|) ----
    const float a  = fmaxf(fabsf(dd) * (-1.4426950408889634f), -126.0f); // -|dd|*log2e
    const float sh = a + 12582912.0f;            // 1.5*2^23 round trick
    const float nf = sh - 12582912.0f;           // n = round(a), exact
    const float fe = a - nf;                     // fe in [-0.5, 0.5], exact
    const float fe2 = fe * fe;
    const float fe4 = fe2 * fe2;
    // e^(fe*ln2): deg-7 Taylor, Estrin
    const float p01 = fmaf(fe, 0.6931471805599453f,  1.0f);
    const float p23 = fmaf(fe, 0.0555041086648216f,  0.2402265069591007f);
    const float p45 = fmaf(fe, 0.0013333558146428443f, 0.009618129107628477f);
    const float p67 = fmaf(fe, 1.5252733804059838e-5f, 1.5403530393381608e-4f);
    const float q0  = fmaf(fe2, p23, p01);
    const float q1  = fmaf(fe2, p67, p45);
    const float pe  = fmaf(fe4, q1, q0);
    // scale = 2^n via bit trick: (bits(sh)<<23) + bits(1.0f)
    const float sc  = __int_as_float((__float_as_int(sh) << 23) + 0x3F800000);
    const float e   = pe * sc;                   // e in (0, 1+eps]
    // ---- t = log1p(e), branchless range split at sqrt(2)-1 ----
    const bool  hi = e > 0.41421356f;
    const float f  = hi ? (e - 1.0f) * 0.5f : e; // f in [-0.2929, 0.4143]
    const float bb = hi ? 0.6931471805599453f : 0.0f;
    const float f2 = f * f;
    const float f4 = f2 * f2;
    const float f8 = f4 * f4;
    // R(f) = log1p(f)/f = sum_{k=0..16} (-1)^k f^k/(k+1), Estrin
    const float s01 = fmaf(f, -0.5f,                 1.0f);
    const float s23 = fmaf(f, -0.25f,                0.3333333333333333f);
    const float s45 = fmaf(f, -0.16666666666666666f, 0.2f);
    const float s67 = fmaf(f, -0.125f,               0.14285714285714285f);
    const float sq0 = fmaf(f2, s23, s01);
    const float sq1 = fmaf(f2, s67, s45);
    const float S0  = fmaf(f4, sq1, sq0);        // c0..c7
    const float t01 = fmaf(f, -0.1f,                 0.1111111111111111f);
    const float t23 = fmaf(f, -0.08333333333333333f, 0.09090909090909091f);
    const float t45 = fmaf(f, -0.07142857142857142f, 0.07692307692307693f);
    const float t67 = fmaf(f, -0.0625f,              0.06666666666666667f);
    const float tq0 = fmaf(f2, t23, t01);
    const float tq1 = fmaf(f2, t67, t45);
    const float T0  = fmaf(f4, tq1, tq0);        // c8..c15
    const float S1  = fmaf(f8, 0.058823529411764705f, T0);  // + c16*f^8
    const float R   = fmaf(f8, S1, S0);
    return fmaf(f, R, bb);                       // t = basef + f*R(f)
}

// One DP step: x1/x2/dd/m/A0 byte-identical to reference; t via fast softplus.
#define STEP(A0, A1, lp, lq, rv) do {                      \
    const float x1_ = (A0) + (lp);                         \
    const float x2_ = (A1) + (lq);                         \
    const float m_  = fmaxf(x1_, x2_);                     \
    const float dd_ = x1_ - x2_;                           \
    const float t_  = softplus_tail(dd_);                  \
    (A1) = m_ + t_;                                        \
    (A0) = (A0) + (lq);                                    \
    (rv) = x1_ - (A1);                                     \
} while (0)

// ---------------------------------------------------------------------------
// Kernel 1: elementwise lp/lq from logits (bit-exact libdevice), [i][b]
// ---------------------------------------------------------------------------
__global__ void k_prep(const float* __restrict__ logits) {
    __shared__ float2 tile[32][33];
    const int tx = threadIdx.x, ty = threadIdx.y;
    const int i0 = blockIdx.x * 32;   // item index base
    const int b0 = blockIdx.y * 32;   // row index base

    #pragma unroll
    for (int r = 0; r < 4; r++) {
        const int b = b0 + ty + r * 8;
        const int i = i0 + tx;
        const float z = logits[(size_t)b * Nn + i];
        // jax.nn.log_sigmoid(z) = -(max(-z,0) + log1p(exp(-|z|)))
        const float sp = fmaxf(-z, 0.0f) + log1pf(expf(-fabsf(z)));
        const float lp = fminf(-sp, -1e-7f);
        const float lq = log1mexp_f(lp);
        tile[ty + r * 8][tx] = make_float2(lp, lq);
    }
    __syncthreads();
    #pragma unroll
    for (int r = 0; r < 4; r++) {
        const int i = i0 + ty + r * 8;
        const int b = b0 + tx;
        g_lplq[(size_t)i * Bsz + b] = tile[tx][ty + r * 8];
    }
}

__global__ void k_pad() {}   // keeps k_scan at ncu's captured launch slot (#6)

// ---------------------------------------------------------------------------
// Kernel 2: sequential forward DP per row -- proven R4 mapping (float2 [i][b]
// loads, CH=16 named double buffers, float4 [b][i] stores), fast softplus.
// ---------------------------------------------------------------------------
__global__ void __launch_bounds__(32, 1) k_scan() {
    const int b = blockIdx.x * 32 + threadIdx.x;
    float4* __restrict__ rrow = (float4*)(g_r + (size_t)b * Nn);
    float A0 = 0.0f;
    float A1 = neg_inf_f();

    float2 bufA[CH], bufB[CH];
    #pragma unroll
    for (int j = 0; j < CH; j++) bufA[j] = g_lplq[(size_t)j * Bsz + b];
    #pragma unroll
    for (int j = 0; j < CH; j++) bufB[j] = g_lplq[(size_t)(CH + j) * Bsz + b];

    for (int c = 0; c < NC; c += 2) {
        {
            float4 acc;
            #pragma unroll
            for (int j = 0; j < CH; j++) {
                float rv;
                STEP(A0, A1, bufA[j].x, bufA[j].y, rv);
                if ((j & 3) == 0) acc.x = rv;
                else if ((j & 3) == 1) acc.y = rv;
                else if ((j & 3) == 2) acc.z = rv;
                else { acc.w = rv; rrow[(c * CH + j) >> 2] = acc; }
            }
        }
        if (c + 2 < NC) {
            #pragma unroll
            for (int j = 0; j < CH; j++)
                bufA[j] = g_lplq[(size_t)((c + 2) * CH + j) * Bsz + b];
        }
        {
            float4 acc;
            #pragma unroll
            for (int j = 0; j < CH; j++) {
                float rv;
                STEP(A0, A1, bufB[j].x, bufB[j].y, rv);
                if ((j & 3) == 0) acc.x = rv;
                else if ((j & 3) == 1) acc.y = rv;
                else if ((j & 3) == 2) acc.z = rv;
                else { acc.w = rv; rrow[((c + 1) * CH + j) >> 2] = acc; }
            }
        }
        if (c + 3 < NC) {
            #pragma unroll
            for (int j = 0; j < CH; j++)
                bufB[j] = g_lplq[(size_t)((c + 3) * CH + j) * Bsz + b];
        }
    }
}

// ---------------------------------------------------------------------------
// Kernel 3 (fused decide+write): one block per row. With K=1, the selected
// item = MAX index i with u_i < sigmoid(p_i - q_i); thresholds after the
// success are exactly 0. Decision math stays full-libdevice (as reference).
// ---------------------------------------------------------------------------
__global__ void __launch_bounds__(256) k_decide_write(const float* __restrict__ noise,
                                                      float4* __restrict__ out) {
    __shared__ int wmax[8];
    __shared__ int s_sel;
    const int row = blockIdx.x;
    const int t   = threadIdx.x;
    const float4* __restrict__ rrow = (const float4*)(g_r + (size_t)row * Nn);
    const float4* __restrict__ urow = (const float4*)(noise + (size_t)row * Nn);

    int sel = -1;
    #pragma unroll
    for (int k = 0; k < 8; k++) {
        const int e  = t + 256 * k;        // float4 index within row (0..2047)
        const float4 rv = rrow[e];
        const float4 uv = urow[e];
        const int i0 = e * 4;
        #pragma unroll
        for (int j = 0; j < 4; j++) {
            float r = (j == 0) ? rv.x : (j == 1) ? rv.y : (j == 2) ? rv.z : rv.w;
            const float u = (j == 0) ? uv.x : (j == 1) ? uv.y : (j == 2) ? uv.z : uv.w;
            r = fminf(r, 0.0f);                       // clamp, ref op order
            const float q = log1mexp_f(r);
            const float d = r - q;
            const float th = 1.0f / (1.0f + expf(-d)); // sigmoid; d=+inf -> 1
            if (u < th) sel = i0 + j;
        }
    }
    #pragma unroll
    for (int s = 16; s > 0; s >>= 1)
        sel = max(sel, __shfl_xor_sync(0xffffffffu, sel, s));
    if ((t & 31) == 0) wmax[t >> 5] = sel;
    __syncthreads();
    if (t == 0) {
        int m = wmax[0];
        #pragma unroll
        for (int w = 1; w < 8; w++) m = max(m, wmax[w]);
        s_sel = m;
    }
    __syncthreads();
    const int s = s_sel;

    #pragma unroll
    for (int k = 0; k < 8; k++) {
        const int e = t + 256 * k;
        const int i = e * 4;
        float4 v;
        v.x = (i     == s) ? 1.0f : 0.0f;
        v.y = (i + 1 == s) ? 1.0f : 0.0f;
        v.z = (i + 2 == s) ? 1.0f : 0.0f;
        v.w = (i + 3 == s) ? 1.0f : 0.0f;
        out[(size_t)row * (Nn / 4) + e] = v;
    }
}

extern "C" void kernel_launch(void* const* d_in, const int* in_sizes, int n_in,
                              void* d_out, int out_size) {
    const float* logits = (const float*)d_in[0];
    const float* noise  = (const float*)d_in[1];
    float4* out = (float4*)d_out;

    dim3 b1(32, 8), g1(Nn / 32, Bsz / 32);
    k_prep<<<g1, b1>>>(logits);
    k_pad<<<1, 32>>>();
    k_pad<<<1, 32>>>();                              // k_scan -> ncu slot #6
    k_scan<<<Bsz / 32, 32>>>();                      // 16 warps, 16 SMs
    k_decide_write<<<Bsz, 256>>>(noise, out);
}

// round 12
// speedup vs baseline: 1.4576x; 1.4576x over previous
#include <cuda_runtime.h>
#include <cstdint>

#define Bsz 512
#define Nn  8192
#define CH  16
#define NC  (Nn / CH)

// Scratch (static __device__ per harness rules)
__device__ float2 g_lplq[(size_t)Bsz * Nn];   // (lp_i, lq_i) transposed [i][b]
__device__ float  g_r   [(size_t)Bsz * Nn];   // r_i = x1_i - A1_i, layout [b][i]

__device__ __forceinline__ float neg_inf_f() { return __int_as_float(0xff800000); }

// log1mexp(x) = log(1 - e^x), x <= 0, matching the reference's branch structure
__device__ __forceinline__ float log1mexp_f(float x) {
    return (x > -0.69314718f) ? logf(-expm1f(x)) : log1pf(-expf(x));
}

__device__ __forceinline__ float rcp_approx(float x) {
    float y; asm("rcp.approx.f32 %0, %1;" : "=f"(y) : "f"(x)); return y;
}

// ---------------------------------------------------------------------------
// Branch-free softplus(-|dd|) = log1p(exp(-|dd|)).
// Engineered to max(chain, 2*n_instr): ~37 instrs (74cy issue floor),
// ~96cy chain, NO branches (libdevice log1pf carries BSSY/BSYNC ~33cy).
//   exp: magic-number round + deg-6 Taylor (rel tail 1.2e-7), Estrin.
//   log1p(e) = 2*atanh(s), s = e/(2+e)  -- no subtraction, one MUFU.RCP
//   (rel ~1e-7), odd deg-11 atanh poly (tail ~6e-8), Estrin.
// Total |dt| <= ~2e-7 -- inside the R8-proven zero-flip envelope (2.5e-7).
// dd=+inf (step 1): a clamps to -126 -> e=2^-126 -> t ~ 1e-38 -> A1 = m + t
// rounds to m exactly (reference has t = 0). No NaN anywhere.
// ---------------------------------------------------------------------------
__device__ __forceinline__ float softplus_tail(float dd) {
    // ---- e = exp2(a), a = max(-|dd|*log2e, -126) ----
    const float a  = fmaxf(fabsf(dd) * (-1.4426950408889634f), -126.0f);
    const float sh = a + 12582912.0f;             // 1.5*2^23 round trick
    const float nf = sh - 12582912.0f;            // n = round(a), exact
    const float fe = a - nf;                      // fe in [-0.5, 0.5], exact
    const float fe2 = fe * fe;
    const float fe4 = fe2 * fe2;
    // e^(fe*ln2): deg-6 Taylor, Estrin
    const float pA = fmaf(fe, 0.6931471805599453f,   1.0f);
    const float pB = fmaf(fe, 0.05550410866482158f,  0.2402265069591007f);
    const float pC = fmaf(fe, 0.0013333558146428443f, 0.009618129107628477f);
    const float pE = fmaf(fe2, 1.5403530393381608e-4f, pC);
    const float pF = fmaf(fe2, pB, pA);
    const float P  = fmaf(fe4, pE, pF);
    const float sc = __int_as_float((__float_as_int(sh) << 23) + 0x3F800000);
    const float e  = P * sc;                      // e in (0, 1+2e-6]
    // ---- t = log1p(e) = 2*atanh(e/(2+e)), s in (0, 1/3] ----
    const float den = e + 2.0f;
    const float s   = e * rcp_approx(den);
    const float s2  = s * s;
    const float v2  = s2 * s2;
    const float v4  = v2 * v2;
    const float qA  = fmaf(s2, 0.3333333333333333f,  1.0f);
    const float qB  = fmaf(s2, 0.14285714285714285f, 0.2f);
    const float qC  = fmaf(s2, 0.09090909090909091f, 0.1111111111111111f);
    const float qE  = fmaf(v2, qB, qA);
    const float R   = fmaf(v4, qC, qE);
    return (s + s) * R;
}

// One DP step: x1/x2/dd/m/A0/A1-add keep exact reference roundings
// (6600-magnitude walk is part of the answer); only t is approximated.
#define STEP(A0, A1, lp, lq, rv) do {                      \
    const float x1_ = (A0) + (lp);                         \
    const float x2_ = (A1) + (lq);                         \
    const float m_  = fmaxf(x1_, x2_);                     \
    const float dd_ = x1_ - x2_;                           \
    const float t_  = softplus_tail(dd_);                  \
    (A1) = m_ + t_;                                        \
    (A0) = (A0) + (lq);                                    \
    (rv) = x1_ - (A1);                                     \
} while (0)

// ---------------------------------------------------------------------------
// Kernel 1: elementwise lp/lq from logits (bit-exact libdevice), [i][b]
// ---------------------------------------------------------------------------
__global__ void k_prep(const float* __restrict__ logits) {
    __shared__ float2 tile[32][33];
    const int tx = threadIdx.x, ty = threadIdx.y;
    const int i0 = blockIdx.x * 32;   // item index base
    const int b0 = blockIdx.y * 32;   // row index base

    #pragma unroll
    for (int r = 0; r < 4; r++) {
        const int b = b0 + ty + r * 8;
        const int i = i0 + tx;
        const float z = logits[(size_t)b * Nn + i];
        // jax.nn.log_sigmoid(z) = -(max(-z,0) + log1p(exp(-|z|)))
        const float sp = fmaxf(-z, 0.0f) + log1pf(expf(-fabsf(z)));
        const float lp = fminf(-sp, -1e-7f);
        const float lq = log1mexp_f(lp);
        tile[ty + r * 8][tx] = make_float2(lp, lq);
    }
    __syncthreads();
    #pragma unroll
    for (int r = 0; r < 4; r++) {
        const int i = i0 + ty + r * 8;
        const int b = b0 + tx;
        g_lplq[(size_t)i * Bsz + b] = tile[tx][ty + r * 8];
    }
}

__global__ void k_pad() {}   // keeps k_scan at ncu's captured launch slot (#6)

// ---------------------------------------------------------------------------
// Kernel 2: sequential forward DP per row -- proven R4 mapping (float2 [i][b]
// loads, CH=16 named double buffers, float4 [b][i] stores).
// ---------------------------------------------------------------------------
__global__ void __launch_bounds__(32, 1) k_scan() {
    const int b = blockIdx.x * 32 + threadIdx.x;
    float4* __restrict__ rrow = (float4*)(g_r + (size_t)b * Nn);
    float A0 = 0.0f;
    float A1 = neg_inf_f();

    float2 bufA[CH], bufB[CH];
    #pragma unroll
    for (int j = 0; j < CH; j++) bufA[j] = g_lplq[(size_t)j * Bsz + b];
    #pragma unroll
    for (int j = 0; j < CH; j++) bufB[j] = g_lplq[(size_t)(CH + j) * Bsz + b];

    for (int c = 0; c < NC; c += 2) {
        {
            float4 acc;
            #pragma unroll
            for (int j = 0; j < CH; j++) {
                float rv;
                STEP(A0, A1, bufA[j].x, bufA[j].y, rv);
                if ((j & 3) == 0) acc.x = rv;
                else if ((j & 3) == 1) acc.y = rv;
                else if ((j & 3) == 2) acc.z = rv;
                else { acc.w = rv; rrow[(c * CH + j) >> 2] = acc; }
            }
        }
        if (c + 2 < NC) {
            #pragma unroll
            for (int j = 0; j < CH; j++)
                bufA[j] = g_lplq[(size_t)((c + 2) * CH + j) * Bsz + b];
        }
        {
            float4 acc;
            #pragma unroll
            for (int j = 0; j < CH; j++) {
                float rv;
                STEP(A0, A1, bufB[j].x, bufB[j].y, rv);
                if ((j & 3) == 0) acc.x = rv;
                else if ((j & 3) == 1) acc.y = rv;
                else if ((j & 3) == 2) acc.z = rv;
                else { acc.w = rv; rrow[((c + 1) * CH + j) >> 2] = acc; }
            }
        }
        if (c + 3 < NC) {
            #pragma unroll
            for (int j = 0; j < CH; j++)
                bufB[j] = g_lplq[(size_t)((c + 3) * CH + j) * Bsz + b];
        }
    }
}

// ---------------------------------------------------------------------------
// Kernel 3 (fused decide+write): one block per row. With K=1, the selected
// item = MAX index i with u_i < sigmoid(p_i - q_i); thresholds after the
// success are exactly 0. Decision math stays full-libdevice (as reference).
// ---------------------------------------------------------------------------
__global__ void __launch_bounds__(256) k_decide_write(const float* __restrict__ noise,
                                                      float4* __restrict__ out) {
    __shared__ int wmax[8];
    __shared__ int s_sel;
    const int row = blockIdx.x;
    const int t   = threadIdx.x;
    const float4* __restrict__ rrow = (const float4*)(g_r + (size_t)row * Nn);
    const float4* __restrict__ urow = (const float4*)(noise + (size_t)row * Nn);

    int sel = -1;
    #pragma unroll
    for (int k = 0; k < 8; k++) {
        const int e  = t + 256 * k;        // float4 index within row (0..2047)
        const float4 rv = rrow[e];
        const float4 uv = urow[e];
        const int i0 = e * 4;
        #pragma unroll
        for (int j = 0; j < 4; j++) {
            float r = (j == 0) ? rv.x : (j == 1) ? rv.y : (j == 2) ? rv.z : rv.w;
            const float u = (j == 0) ? uv.x : (j == 1) ? uv.y : (j == 2) ? uv.z : uv.w;
            r = fminf(r, 0.0f);                       // clamp, ref op order
            const float q = log1mexp_f(r);
            const float d = r - q;
            const float th = 1.0f / (1.0f + expf(-d)); // sigmoid; d=+inf -> 1
            if (u < th) sel = i0 + j;
        }
    }
    #pragma unroll
    for (int s = 16; s > 0; s >>= 1)
        sel = max(sel, __shfl_xor_sync(0xffffffffu, sel, s));
    if ((t & 31) == 0) wmax[t >> 5] = sel;
    __syncthreads();
    if (t == 0) {
        int m = wmax[0];
        #pragma unroll
        for (int w = 1; w < 8; w++) m = max(m, wmax[w]);
        s_sel = m;
    }
    __syncthreads();
    const int s = s_sel;

    #pragma unroll
    for (int k = 0; k < 8; k++) {
        const int e = t + 256 * k;
        const int i = e * 4;
        float4 v;
        v.x = (i     == s) ? 1.0f : 0.0f;
        v.y = (i + 1 == s) ? 1.0f : 0.0f;
        v.z = (i + 2 == s) ? 1.0f : 0.0f;
        v.w = (i + 3 == s) ? 1.0f : 0.0f;
        out[(size_t)row * (Nn / 4) + e] = v;
    }
}

extern "C" void kernel_launch(void* const* d_in, const int* in_sizes, int n_in,
                              void* d_out, int out_size) {
    const float* logits = (const float*)d_in[0];
    const float* noise  = (const float*)d_in[1];
    float4* out = (float4*)d_out;

    dim3 b1(32, 8), g1(Nn / 32, Bsz / 32);
    k_prep<<<g1, b1>>>(logits);
    k_pad<<<1, 32>>>();
    k_pad<<<1, 32>>>();                              // k_scan -> ncu slot #6
    k_scan<<<Bsz / 32, 32>>>();                      // 16 warps, 16 SMs
    k_decide_write<<<Bsz, 256>>>(noise, out);
}

// round 13
// speedup vs baseline: 1.5864x; 1.0884x over previous
#include <cuda_runtime.h>
#include <cstdint>

#define Bsz 512
#define Nn  8192
#define CH  16
#define NC  (Nn / CH)

// Scratch (static __device__ per harness rules)
__device__ float2 g_lplq[(size_t)Bsz * Nn];   // (lp_i, lq_i) transposed [i][b]
__device__ float  g_r   [(size_t)Bsz * Nn];   // r_i = x1_i - A1_i, layout [b][i]

__device__ __forceinline__ float neg_inf_f() { return __int_as_float(0xff800000); }

// log1mexp(x) = log(1 - e^x), x <= 0, matching the reference's branch structure
__device__ __forceinline__ float log1mexp_f(float x) {
    return (x > -0.69314718f) ? logf(-expm1f(x)) : log1pf(-expf(x));
}

// ---------------------------------------------------------------------------
// Pure-FMA/ALU softplus(-|dd|) = log1p(exp(-|dd|)).
// NO MUFU (R8/R12: MUFU in a 1-warp chain costs ~50-70cy effective, not 16),
// NO predicates/branches (R11 suspect: ternaries -> FSETP/BSSY overhead).
// Range split is done with a sign-bit mask + LOP3-style integer select.
//   exp: magic-number round + deg-6 Taylor (rel 1.2e-7), Estrin.
//   log1p: split at sqrt2-1; f in [-0.293, 0.414]; deg-15 Taylor (exact 1/k
//   coefficients, tail 4.4e-8), Estrin depth 20cy.
// Total |dt| <= ~3e-7 typical ~1e-7 -- R8-proven envelope scale.
// dd=+inf (step 1): a clamps to -126 -> e=2^-126 -> t ~= e -> A1 = m exactly.
// ---------------------------------------------------------------------------
__device__ __forceinline__ float softplus_tail(float dd) {
    // ---- e = exp2(a), a = max(-|dd|*log2e, -126) ----
    const float a  = fmaxf(fabsf(dd) * (-1.4426950408889634f), -126.0f);
    const float sh = a + 12582912.0f;             // 1.5*2^23 round trick
    const float nf = sh - 12582912.0f;            // n = round(a), exact
    const float fe = a - nf;                      // fe in [-0.5, 0.5], exact
    const float fe2 = fe * fe;
    const float fe4 = fe2 * fe2;
    const float pA = fmaf(fe, 0.6931471805599453f,   1.0f);
    const float pB = fmaf(fe, 0.05550410866482158f,  0.2402265069591007f);
    const float pC = fmaf(fe, 0.0013333558146428443f, 0.009618129107628477f);
    const float pE = fmaf(fe2, 1.5403530393381608e-4f, pC);
    const float pF = fmaf(fe2, pB, pA);
    const float P  = fmaf(fe4, pE, pF);
    const float sc = __int_as_float((__float_as_int(sh) << 23) + 0x3F800000);
    const float e  = P * sc;                      // e in (0, 1+2e-6]

    // ---- branchless split at th = sqrt2-1 via sign-bit mask ----
    const float d   = e - 0.41421356237309503f;
    const int   msk = __float_as_int(d) >> 31;    // all-ones iff e < th (low branch)
    const float fal = fmaf(e, 0.5f, -0.5f);       // (e-1)/2 for the high branch
    const int   fbits = (__float_as_int(e) & msk) | (__float_as_int(fal) & ~msk);
    const float f   = __int_as_float(fbits);      // f in [-0.293, 0.414]
    const float bb  = __int_as_float(0x3F317218 & ~msk);  // ln2 on high branch, else 0

    // ---- R(f) = log1p(f)/f, deg-15 Taylor, Estrin ----
    const float f2 = f * f;
    const float f4 = f2 * f2;
    const float f8 = f4 * f4;
    const float p0 = fmaf(f, -0.5f,                 1.0f);
    const float p1 = fmaf(f, -0.25f,                0.3333333333333333f);
    const float p2 = fmaf(f, -0.16666666666666666f, 0.2f);
    const float p3 = fmaf(f, -0.125f,               0.14285714285714285f);
    const float p4 = fmaf(f, -0.1f,                 0.1111111111111111f);
    const float p5 = fmaf(f, -0.08333333333333333f, 0.09090909090909091f);
    const float p6 = fmaf(f, -0.07142857142857142f, 0.07692307692307693f);
    const float p7 = fmaf(f, -0.0625f,              0.06666666666666667f);
    const float q0 = fmaf(f2, p1, p0);
    const float q1 = fmaf(f2, p3, p2);
    const float q2 = fmaf(f2, p5, p4);
    const float q3 = fmaf(f2, p7, p6);
    const float o0 = fmaf(f4, q1, q0);
    const float o1 = fmaf(f4, q3, q2);
    const float R  = fmaf(f8, o1, o0);
    return fmaf(f, R, bb);                        // t = bb + f*R(f)
}

// One DP step: x1/x2/dd/m/A0/A1-add keep exact reference roundings;
// only the softplus tail is approximated (R8-proven safe envelope).
#define STEP(A0, A1, lp, lq, rv) do {                      \
    const float x1_ = (A0) + (lp);                         \
    const float x2_ = (A1) + (lq);                         \
    const float m_  = fmaxf(x1_, x2_);                     \
    const float dd_ = x1_ - x2_;                           \
    const float t_  = softplus_tail(dd_);                  \
    (A1) = m_ + t_;                                        \
    (A0) = (A0) + (lq);                                    \
    (rv) = x1_ - (A1);                                     \
} while (0)

// ---------------------------------------------------------------------------
// Kernel 1: elementwise lp/lq from logits (bit-exact libdevice), [i][b]
// ---------------------------------------------------------------------------
__global__ void k_prep(const float* __restrict__ logits) {
    __shared__ float2 tile[32][33];
    const int tx = threadIdx.x, ty = threadIdx.y;
    const int i0 = blockIdx.x * 32;   // item index base
    const int b0 = blockIdx.y * 32;   // row index base

    #pragma unroll
    for (int r = 0; r < 4; r++) {
        const int b = b0 + ty + r * 8;
        const int i = i0 + tx;
        const float z = logits[(size_t)b * Nn + i];
        // jax.nn.log_sigmoid(z) = -(max(-z,0) + log1p(exp(-|z|)))
        const float sp = fmaxf(-z, 0.0f) + log1pf(expf(-fabsf(z)));
        const float lp = fminf(-sp, -1e-7f);
        const float lq = log1mexp_f(lp);
        tile[ty + r * 8][tx] = make_float2(lp, lq);
    }
    __syncthreads();
    #pragma unroll
    for (int r = 0; r < 4; r++) {
        const int i = i0 + ty + r * 8;
        const int b = b0 + tx;
        g_lplq[(size_t)i * Bsz + b] = tile[tx][ty + r * 8];
    }
}

__global__ void k_pad() {}   // keeps k_scan at ncu's captured launch slot (#6)

// ---------------------------------------------------------------------------
// Kernel 2: sequential forward DP per row -- proven R4 mapping (float2 [i][b]
// loads, CH=16 named double buffers, float4 [b][i] stores).
// ---------------------------------------------------------------------------
__global__ void __launch_bounds__(32, 1) k_scan() {
    const int b = blockIdx.x * 32 + threadIdx.x;
    float4* __restrict__ rrow = (float4*)(g_r + (size_t)b * Nn);
    float A0 = 0.0f;
    float A1 = neg_inf_f();

    float2 bufA[CH], bufB[CH];
    #pragma unroll
    for (int j = 0; j < CH; j++) bufA[j] = g_lplq[(size_t)j * Bsz + b];
    #pragma unroll
    for (int j = 0; j < CH; j++) bufB[j] = g_lplq[(size_t)(CH + j) * Bsz + b];

    for (int c = 0; c < NC; c += 2) {
        {
            float4 acc;
            #pragma unroll
            for (int j = 0; j < CH; j++) {
                float rv;
                STEP(A0, A1, bufA[j].x, bufA[j].y, rv);
                if ((j & 3) == 0) acc.x = rv;
                else if ((j & 3) == 1) acc.y = rv;
                else if ((j & 3) == 2) acc.z = rv;
                else { acc.w = rv; rrow[(c * CH + j) >> 2] = acc; }
            }
        }
        if (c + 2 < NC) {
            #pragma unroll
            for (int j = 0; j < CH; j++)
                bufA[j] = g_lplq[(size_t)((c + 2) * CH + j) * Bsz + b];
        }
        {
            float4 acc;
            #pragma unroll
            for (int j = 0; j < CH; j++) {
                float rv;
                STEP(A0, A1, bufB[j].x, bufB[j].y, rv);
                if ((j & 3) == 0) acc.x = rv;
                else if ((j & 3) == 1) acc.y = rv;
                else if ((j & 3) == 2) acc.z = rv;
                else { acc.w = rv; rrow[((c + 1) * CH + j) >> 2] = acc; }
            }
        }
        if (c + 3 < NC) {
            #pragma unroll
            for (int j = 0; j < CH; j++)
                bufB[j] = g_lplq[(size_t)((c + 3) * CH + j) * Bsz + b];
        }
    }
}

// ---------------------------------------------------------------------------
// Kernel 3 (fused decide+write): one block per row. With K=1, the selected
// item = MAX index i with u_i < sigmoid(p_i - q_i); thresholds after the
// success are exactly 0. Decision math stays full-libdevice (as reference).
// ---------------------------------------------------------------------------
__global__ void __launch_bounds__(256) k_decide_write(const float* __restrict__ noise,
                                                      float4* __restrict__ out) {
    __shared__ int wmax[8];
    __shared__ int s_sel;
    const int row = blockIdx.x;
    const int t   = threadIdx.x;
    const float4* __restrict__ rrow = (const float4*)(g_r + (size_t)row * Nn);
    const float4* __restrict__ urow = (const float4*)(noise + (size_t)row * Nn);

    int sel = -1;
    #pragma unroll
    for (int k = 0; k < 8; k++) {
        const int e  = t + 256 * k;        // float4 index within row (0..2047)
        const float4 rv = rrow[e];
        const float4 uv = urow[e];
        const int i0 = e * 4;
        #pragma unroll
        for (int j = 0; j < 4; j++) {
            float r = (j == 0) ? rv.x : (j == 1) ? rv.y : (j == 2) ? rv.z : rv.w;
            const float u = (j == 0) ? uv.x : (j == 1) ? uv.y : (j == 2) ? uv.z : uv.w;
            r = fminf(r, 0.0f);                       // clamp, ref op order
            const float q = log1mexp_f(r);
            const float d = r - q;
            const float th = 1.0f / (1.0f + expf(-d)); // sigmoid; d=+inf -> 1
            if (u < th) sel = i0 + j;
        }
    }
    #pragma unroll
    for (int s = 16; s > 0; s >>= 1)
        sel = max(sel, __shfl_xor_sync(0xffffffffu, sel, s));
    if ((t & 31) == 0) wmax[t >> 5] = sel;
    __syncthreads();
    if (t == 0) {
        int m = wmax[0];
        #pragma unroll
        for (int w = 1; w < 8; w++) m = max(m, wmax[w]);
        s_sel = m;
    }
    __syncthreads();
    const int s = s_sel;

    #pragma unroll
    for (int k = 0; k < 8; k++) {
        const int e = t + 256 * k;
        const int i = e * 4;
        float4 v;
        v.x = (i     == s) ? 1.0f : 0.0f;
        v.y = (i + 1 == s) ? 1.0f : 0.0f;
        v.z = (i + 2 == s) ? 1.0f : 0.0f;
        v.w = (i + 3 == s) ? 1.0f : 0.0f;
        out[(size_t)row * (Nn / 4) + e] = v;
    }
}

extern "C" void kernel_launch(void* const* d_in, const int* in_sizes, int n_in,
                              void* d_out, int out_size) {
    const float* logits = (const float*)d_in[0];
    const float* noise  = (const float*)d_in[1];
    float4* out = (float4*)d_out;

    dim3 b1(32, 8), g1(Nn / 32, Bsz / 32);
    k_prep<<<g1, b1>>>(logits);
    k_pad<<<1, 32>>>();
    k_pad<<<1, 32>>>();                              // k_scan -> ncu slot #6
    k_scan<<<Bsz / 32, 32>>>();                      // 16 warps, 16 SMs
    k_decide_write<<<Bsz, 256>>>(noise, out);
}